// round 15
// baseline (speedup 1.0000x reference)
#include <cuda_runtime.h>
#include <cstdint>

#define Bn    16
#define NCn   80
#define An    33600
#define QAn   (An/4)          /* 8400 quads per frame */
#define FBLK  33              /* 33*256 = 8448 >= 8400 */
#define PRE   750
#define POST  30
#define CH    256
#define NBIN  2048            /* bins: bits(1-s)>>19, clamped */
#define BCAP  128             /* slots per bucket */
#define GBIN  1888u           /* scatter threshold bin; validated via g_cnt */

#define OUT_CLS_OFF  0
#define OUT_REG_OFF  (Bn*POST*CH)
#define OUT_BOX_OFF  (2*Bn*POST*CH)
#define OUT_SC_OFF   (2*Bn*POST*CH + Bn*POST*4)

__device__ float              g_maxs[Bn * An];
__device__ int                g_cls[Bn * An];
__device__ unsigned           g_bcnt[Bn * NBIN];   // zero at load; select resets
__device__ int                g_cnt[Bn];           // counted totals; select resets
__device__ unsigned long long g_bucket[(size_t)Bn * NBIN * BCAP];

static __device__ __forceinline__ unsigned score_bin(float s) {
    unsigned v = __float_as_uint(1.0f - s) >> 19;  // ascending bin <=> descending score
    return v < (NBIN - 1) ? v : (NBIN - 1);
}

// ---------------------------------------------------------------------------
// K1 (fused): streaming max+argmax over 80 classes + thresholded
// bucket-scatter tail on register values (measured-good R14 form).
// ---------------------------------------------------------------------------
__global__ __launch_bounds__(256) void k_max_scatter(const float* __restrict__ raw) {
    const int b = blockIdx.y;
    const int q = blockIdx.x * 256 + threadIdx.x;
    const bool valid = (q < QAn);
    const int qc = valid ? q : (QAn - 1);
    const int lane = (int)(threadIdx.x & 31);

    const float* base = raw + (size_t)b * 84 * An + (size_t)4 * An;

    float4 best = __ldg((const float4*)base + qc);
    int4 bi = make_int4(0, 0, 0, 0);
#pragma unroll 4
    for (int c = 1; c < NCn; ++c) {
        float4 v = __ldg((const float4*)(base + (size_t)c * An) + qc);
        if (v.x > best.x) { best.x = v.x; bi.x = c; }
        if (v.y > best.y) { best.y = v.y; bi.y = c; }
        if (v.z > best.z) { best.z = v.z; bi.z = c; }
        if (v.w > best.w) { best.w = v.w; bi.w = c; }
    }
    if (valid) {
        ((float4*)g_maxs)[b * QAn + q] = best;
        ((int4*)g_cls)[b * QAn + q] = bi;
    }

    float sv[4] = {best.x, best.y, best.z, best.w};
    unsigned mycnt = 0;
#pragma unroll
    for (int l = 0; l < 4; ++l) {
        unsigned bin = score_bin(sv[l]);
        unsigned d = (valid && bin <= GBIN) ? bin : 0xFFFFFFFFu;
        unsigned grp = __match_any_sync(0xFFFFFFFFu, d);
        if (d != 0xFFFFFFFFu) {
            ++mycnt;
            int leader = __ffs(grp) - 1;
            unsigned rank = __popc(grp & ((1u << lane) - 1u));
            unsigned basep;
            if (lane == leader)
                basep = atomicAdd(&g_bcnt[b * NBIN + d], (unsigned)__popc(grp));
            basep = __shfl_sync(grp, basep, leader);
            unsigned slot = basep + rank;
            if (slot < BCAP) {
                int a = q * 4 + l;
                g_bucket[((size_t)b * NBIN + d) * BCAP + slot] =
                    ((unsigned long long)__float_as_uint(sv[l]) << 32) | (unsigned)(~a);
            }
        }
    }
#pragma unroll
    for (int o = 16; o > 0; o >>= 1)
        mycnt += __shfl_down_sync(0xFFFFFFFFu, mycnt, o);
    if (lane == 0 && mycnt) atomicAdd(&g_cnt[b], (int)mycnt);
}

// ---------------------------------------------------------------------------
// K2: per-frame — pivot, gather + rank placement, PER-CLASS PARALLEL exact
// NMS, PARALLEL stable partition, fused gather. Resets state for replay.
// ---------------------------------------------------------------------------
__global__ __launch_bounds__(1024) void k_select(const float* __restrict__ raw,
                                                 const float* __restrict__ vid,
                                                 const float* __restrict__ reg,
                                                 float* __restrict__ out) {
    const int b = blockIdx.x;
    const int tid = threadIdx.x;
    const int T = 1024;

    __shared__ unsigned long long keys[1024];
    __shared__ unsigned cnts[NBIN];
    __shared__ unsigned prefs[NBIN];
    __shared__ float bx1[PRE], by1[PRE], bx2[PRE], by2[PRE], barea[PRE];
    __shared__ int bcls[PRE];
    __shared__ int keep[PRE];
    __shared__ int members[PRE];
    __shared__ int ccnt[NCn], cstart[NCn], coff[NCn];
    __shared__ int sh_final[POST];
    __shared__ unsigned hist[256];
    __shared__ unsigned wsum[32];
    __shared__ unsigned long long sh_prefix;
    __shared__ unsigned sh_k;
    __shared__ int sh_pos, sh_maxbits;
    __shared__ int sh_p, sh_total, sh_over;

    const float* ms = g_maxs + (size_t)b * An;
    const int* cl = g_cls + (size_t)b * An;
    unsigned* BC = g_bcnt + (size_t)b * NBIN;

    int counted = g_cnt[b];

    // ---- load counts (2 bins/thread), block scan, pivot bin ----
    uint2 c2 = ((const uint2*)BC)[tid];
    cnts[2 * tid] = c2.x;
    cnts[2 * tid + 1] = c2.y;
    unsigned s = c2.x + c2.y;

    unsigned lane = tid & 31, wid = tid >> 5;
    unsigned v = s;
#pragma unroll
    for (int o = 1; o < 32; o <<= 1) {
        unsigned n = __shfl_up_sync(0xFFFFFFFFu, v, o);
        if (lane >= o) v += n;
    }
    if (lane == 31) wsum[wid] = v;
    if (tid == 0) { sh_over = 0; sh_p = -1; sh_total = 0; }
    __syncthreads();
    if (wid == 0) {
        unsigned w = wsum[lane];
#pragma unroll
        for (int o = 1; o < 32; o <<= 1) {
            unsigned n = __shfl_up_sync(0xFFFFFFFFu, w, o);
            if (lane >= o) w += n;
        }
        wsum[lane] = w;
    }
    __syncthreads();
    unsigned incl = v + (wid ? wsum[wid - 1] : 0u);
    unsigned excl = incl - s;
    prefs[2 * tid] = excl;
    prefs[2 * tid + 1] = excl + c2.x;

    if (excl < PRE && incl >= PRE) {
        int p = (excl + c2.x >= PRE) ? (2 * tid) : (2 * tid + 1);
        sh_p = p;
        sh_total = (int)(prefs[p] + cnts[p]);
    }
    __syncthreads();
    int p = sh_p;
    int total = sh_total;
    if ((int)(2 * tid) <= p && c2.x > BCAP) sh_over = 1;
    if ((int)(2 * tid + 1) <= p && c2.y > BCAP) sh_over = 1;
    __syncthreads();

    bool fastpath = (counted >= PRE) && (p >= 0) && (total <= 1024) && !sh_over;

    if (fastpath) {
        // ---- gather + rank placement (bins strictly score-separated) ----
        if (tid < total) {
            int lo = 0, hi = p;
            while (lo < hi) {
                int mid = (lo + hi + 1) >> 1;
                if (prefs[mid] <= (unsigned)tid) lo = mid; else hi = mid - 1;
            }
            unsigned k = (unsigned)tid - prefs[lo];
            const unsigned long long* src = g_bucket + ((size_t)b * NBIN + lo) * BCAP;
            unsigned long long key = src[k];
            unsigned cnt = cnts[lo];
            int rank = 0;
            for (unsigned m = 0; m < cnt; ++m)
                rank += (src[m] > key);
            keys[prefs[lo] + rank] = key;
        } else {
            keys[tid] = 0ULL;
        }
        __syncthreads();
    } else {
        // ---- exact fallback: 8-pass 64-bit radix select + block bitonic ----
        unsigned long long prefix = 0ULL;
        unsigned kk = PRE;
        const int ITER = (An + T - 1) / T;
        for (int pass = 0; pass < 8; ++pass) {
            int shift = 56 - pass * 8;
            unsigned long long hi_mask = (pass == 0) ? 0ULL : (~0ULL << (unsigned)(shift + 8));
            for (int i = tid; i < 256; i += T) hist[i] = 0;
            __syncthreads();
            for (int it = 0; it < ITER; ++it) {
                int a = it * T + tid;
                if (a < An) {
                    unsigned long long key =
                        ((unsigned long long)__float_as_uint(ms[a]) << 32) | (unsigned)(~a);
                    if ((key & hi_mask) == prefix)
                        atomicAdd(&hist[(unsigned)(key >> shift) & 255u], 1u);
                }
            }
            __syncthreads();
            if (tid == 0) {
                unsigned cum = 0; int d = 255;
                for (; d >= 0; --d) {
                    unsigned c = hist[d];
                    if (cum + c >= kk) break;
                    cum += c;
                }
                if (d < 0) d = 0;
                prefix |= ((unsigned long long)d) << shift;
                kk -= cum;
                sh_prefix = prefix; sh_k = kk;
            }
            __syncthreads();
            prefix = sh_prefix; kk = sh_k;
            __syncthreads();
        }
        if (tid == 0) sh_pos = 0;
        __syncthreads();
        for (int a = tid; a < An; a += T) {
            unsigned long long key =
                ((unsigned long long)__float_as_uint(ms[a]) << 32) | (unsigned)(~a);
            if (key >= prefix) {
                int pos = atomicAdd(&sh_pos, 1);
                if (pos < 1024) keys[pos] = key;
            }
        }
        __syncthreads();
        int cpos = sh_pos; if (cpos > 1024) cpos = 1024;
        for (int i = cpos + tid; i < 1024; i += T) keys[i] = 0ULL;
        __syncthreads();
        unsigned long long vv = keys[tid];
        for (int k2 = 2; k2 <= 1024; k2 <<= 1) {
            bool dirmax = ((tid & k2) == 0);
            for (int j = k2 >> 1; j >= 1; j >>= 1) {
                unsigned long long o;
                if (j >= 32) {
                    keys[tid] = vv;
                    __syncthreads();
                    o = keys[tid ^ j];
                    __syncthreads();
                } else {
                    o = __shfl_xor_sync(0xFFFFFFFFu, vv, j);
                }
                bool lower = ((tid & j) == 0);
                bool takeMax = (lower == dirmax);
                bool gt = (vv > o);
                vv = (takeMax == gt) ? vv : o;
            }
        }
        keys[tid] = vv;
        __syncthreads();
    }

    // reset global state for graph replay (after all reads of BC)
    ((uint2*)BC)[tid] = make_uint2(0, 0);
    if (tid == 0) g_cnt[b] = 0;

    // ---- boxes/classes for sorted top-750; max coordinate ----
    if (tid == 0) sh_maxbits = 0;
    if (tid < NCn) ccnt[tid] = 0;
    __syncthreads();
    if (tid < PRE) {
        int i = tid;
        int a = (int)(~(unsigned)(keys[i] & 0xFFFFFFFFULL));
        const float* rb = raw + (size_t)b * 84 * An;
        float x1 = rb[0 * (size_t)An + a];
        float y1 = rb[1 * (size_t)An + a];
        float x2 = rb[2 * (size_t)An + a];
        float y2 = rb[3 * (size_t)An + a];
        bx1[i] = x1; by1[i] = y1; bx2[i] = x2; by2[i] = y2;
        bcls[i] = cl[a];
        float m = fmaxf(fmaxf(x1, y1), fmaxf(x2, y2));
        atomicMax(&sh_maxbits, __float_as_int(m));
        keep[i] = 1;
        atomicAdd(&ccnt[cl[a]], 1);
    }
    __syncthreads();

    float off_scale = __int_as_float(sh_maxbits) + 1.0f;
    if (tid < PRE) {
        int i = tid;
        float off = (float)bcls[i] * off_scale;
        float x1 = bx1[i] + off, y1 = by1[i] + off;
        float x2 = bx2[i] + off, y2 = by2[i] + off;
        bx1[i] = x1; by1[i] = y1; bx2[i] = x2; by2[i] = y2;
        barea[i] = (x2 - x1) * (y2 - y1);
    }
    // warp-parallel class prefix (warp 0, 3 bins/lane: 32*3 >= 80)
    if (tid < 32) {
        int l0 = tid * 3;
        int v0 = (l0 + 0 < NCn) ? ccnt[l0 + 0] : 0;
        int v1 = (l0 + 1 < NCn) ? ccnt[l0 + 1] : 0;
        int v2 = (l0 + 2 < NCn) ? ccnt[l0 + 2] : 0;
        int lsum = v0 + v1 + v2;
        int sc = lsum;
#pragma unroll
        for (int o = 1; o < 32; o <<= 1) {
            int n = __shfl_up_sync(0xFFFFFFFFu, sc, o);
            if ((int)tid >= o) sc += n;
        }
        int ex = sc - lsum;
        if (l0 + 0 < NCn) { cstart[l0 + 0] = ex;           coff[l0 + 0] = ex; }
        if (l0 + 1 < NCn) { cstart[l0 + 1] = ex + v0;      coff[l0 + 1] = ex + v0; }
        if (l0 + 2 < NCn) { cstart[l0 + 2] = ex + v0 + v1; coff[l0 + 2] = ex + v0 + v1; }
    }
    __syncthreads();

    // ---- per-class parallel exact NMS ----
    if (tid < PRE) {
        int pos = atomicAdd(&coff[bcls[tid]], 1);
        members[pos] = tid;
    }
    __syncthreads();
    if (tid < NCn) {
        int s0 = cstart[tid], n = ccnt[tid];
        // insertion sort member indices ascending (= score order)
        for (int a2 = 1; a2 < n; ++a2) {
            int mv = members[s0 + a2];
            int b2 = a2 - 1;
            while (b2 >= 0 && members[s0 + b2] > mv) {
                members[s0 + b2 + 1] = members[s0 + b2]; --b2;
            }
            members[s0 + b2 + 1] = mv;
        }
        // exact greedy suppression within the class (classes independent)
        for (int ii = 0; ii < n; ++ii) {
            int i = members[s0 + ii];
            if (!keep[i]) continue;
            float X1 = bx1[i], Y1 = by1[i], X2 = bx2[i], Y2 = by2[i], AR = barea[i];
            for (int jj = ii + 1; jj < n; ++jj) {
                int j = members[s0 + jj];
                if (!keep[j]) continue;
                float iw = fmaxf(fminf(X2, bx2[j]) - fmaxf(X1, bx1[j]), 0.0f);
                float ih = fmaxf(fminf(Y2, by2[j]) - fmaxf(Y1, by1[j]), 0.0f);
                float inter = iw * ih;
                float iou = __fdiv_rn(inter, AR + barea[j] - inter);
                if (iou > 0.4f) keep[j] = 0;
            }
        }
    }
    __syncthreads();

    // ---- parallel stable partition via block scan over keep[] ----
    {
        int kv = (tid < PRE) ? keep[tid] : 0;
        int sc = kv;
#pragma unroll
        for (int o = 1; o < 32; o <<= 1) {
            int n = __shfl_up_sync(0xFFFFFFFFu, sc, o);
            if ((int)lane >= o) sc += n;
        }
        if (lane == 31) wsum[wid] = (unsigned)sc;
        __syncthreads();
        if (wid == 0) {
            int w = (int)wsum[lane];
#pragma unroll
            for (int o = 1; o < 32; o <<= 1) {
                int n = __shfl_up_sync(0xFFFFFFFFu, w, o);
                if ((int)lane >= o) w += n;
            }
            wsum[lane] = (unsigned)w;
        }
        __syncthreads();
        int kincl = sc + (wid ? (int)wsum[wid - 1] : 0);
        int kexcl = kincl - kv;
        int keptTotal = (int)wsum[31];
        if (tid < PRE) {
            int r = kv ? kexcl : (keptTotal + ((int)tid - kexcl));
            if (r < POST) sh_final[r] = tid;
        }
    }
    __syncthreads();

    // ---- fused gather ----
    for (int w2 = tid; w2 < POST * 128; w2 += T) {
        int c = w2 >> 7;
        int f = w2 & 127;
        int i = sh_final[c];
        int a = (int)(~(unsigned)(keys[i] & 0xFFFFFFFFULL));
        size_t r = (size_t)b * POST + c;
        size_t row = ((size_t)b * An + a) * CH;
        if (f < 64)
            ((float4*)(out + OUT_CLS_OFF))[r * 64 + f] = __ldg((const float4*)(vid + row) + f);
        else
            ((float4*)(out + OUT_REG_OFF))[r * 64 + (f - 64)] = __ldg((const float4*)(reg + row) + (f - 64));
    }
    if (tid < POST * 4) {
        int c = tid >> 2, d = tid & 3;
        int i = sh_final[c];
        int a = (int)(~(unsigned)(keys[i] & 0xFFFFFFFFULL));
        out[OUT_BOX_OFF + (b * POST + c) * 4 + d] = raw[(size_t)b * 84 * An + (size_t)d * An + a];
    }
    if (tid >= 128 && tid < 128 + POST) {
        int c = tid - 128;
        int i = sh_final[c];
        out[OUT_SC_OFF + b * POST + c] = __uint_as_float((unsigned)(keys[i] >> 32));
    }
}

// ---------------------------------------------------------------------------
extern "C" void kernel_launch(void* const* d_in, const int* in_sizes, int n_in,
                              void* d_out, int out_size) {
    const float* raw = (const float*)d_in[0];
    const float* vid = (const float*)d_in[1];
    const float* reg = (const float*)d_in[2];
    float* out = (float*)d_out;

    dim3 g1(FBLK, Bn);
    k_max_scatter<<<g1, 256>>>(raw);
    k_select<<<Bn, 1024>>>(raw, vid, reg, out);
}

// round 16
// speedup vs baseline: 1.9905x; 1.9905x over previous
#include <cuda_runtime.h>
#include <cstdint>

#define Bn    16
#define NCn   80
#define An    33600
#define QAn   (An/4)          /* 8400 quads per frame */
#define FBLK  33              /* 33*256 = 8448 >= 8400 */
#define PRE   750
#define POST  30
#define CH    256
#define NBIN  2048            /* bins: bits(1-s)>>19, clamped */
#define BCAP  128             /* slots per bucket */
#define GBIN  1888u           /* scatter threshold bin; validated via g_cnt */

#define OUT_CLS_OFF  0
#define OUT_REG_OFF  (Bn*POST*CH)
#define OUT_BOX_OFF  (2*Bn*POST*CH)
#define OUT_SC_OFF   (2*Bn*POST*CH + Bn*POST*4)

__device__ float              g_maxs[Bn * An];
__device__ int                g_cls[Bn * An];
__device__ unsigned           g_bcnt[Bn * NBIN];   // zero at load; select resets
__device__ int                g_cnt[Bn];           // counted totals; select resets
__device__ unsigned long long g_bucket[(size_t)Bn * NBIN * BCAP];

static __device__ __forceinline__ unsigned score_bin(float s) {
    unsigned v = __float_as_uint(1.0f - s) >> 19;  // ascending bin <=> descending score
    return v < (NBIN - 1) ? v : (NBIN - 1);
}

// ---------------------------------------------------------------------------
// K1 (fused): streaming max+argmax over 80 classes + thresholded
// bucket-scatter tail on register values (measured-good R14 form).
// ---------------------------------------------------------------------------
__global__ __launch_bounds__(256) void k_max_scatter(const float* __restrict__ raw) {
    const int b = blockIdx.y;
    const int q = blockIdx.x * 256 + threadIdx.x;
    const bool valid = (q < QAn);
    const int qc = valid ? q : (QAn - 1);
    const int lane = (int)(threadIdx.x & 31);

    const float* base = raw + (size_t)b * 84 * An + (size_t)4 * An;

    float4 best = __ldg((const float4*)base + qc);
    int4 bi = make_int4(0, 0, 0, 0);
#pragma unroll 4
    for (int c = 1; c < NCn; ++c) {
        float4 v = __ldg((const float4*)(base + (size_t)c * An) + qc);
        if (v.x > best.x) { best.x = v.x; bi.x = c; }
        if (v.y > best.y) { best.y = v.y; bi.y = c; }
        if (v.z > best.z) { best.z = v.z; bi.z = c; }
        if (v.w > best.w) { best.w = v.w; bi.w = c; }
    }
    if (valid) {
        ((float4*)g_maxs)[b * QAn + q] = best;
        ((int4*)g_cls)[b * QAn + q] = bi;
    }

    float sv[4] = {best.x, best.y, best.z, best.w};
    unsigned mycnt = 0;
#pragma unroll
    for (int l = 0; l < 4; ++l) {
        unsigned bin = score_bin(sv[l]);
        unsigned d = (valid && bin <= GBIN) ? bin : 0xFFFFFFFFu;
        unsigned grp = __match_any_sync(0xFFFFFFFFu, d);
        if (d != 0xFFFFFFFFu) {
            ++mycnt;
            int leader = __ffs(grp) - 1;
            unsigned rank = __popc(grp & ((1u << lane) - 1u));
            unsigned basep;
            if (lane == leader)
                basep = atomicAdd(&g_bcnt[b * NBIN + d], (unsigned)__popc(grp));
            basep = __shfl_sync(grp, basep, leader);
            unsigned slot = basep + rank;
            if (slot < BCAP) {
                int a = q * 4 + l;
                g_bucket[((size_t)b * NBIN + d) * BCAP + slot] =
                    ((unsigned long long)__float_as_uint(sv[l]) << 32) | (unsigned)(~a);
            }
        }
    }
#pragma unroll
    for (int o = 16; o > 0; o >>= 1)
        mycnt += __shfl_down_sync(0xFFFFFFFFu, mycnt, o);
    if (lane == 0 && mycnt) atomicAdd(&g_cnt[b], (int)mycnt);
}

// ---------------------------------------------------------------------------
// K2: per-frame — pivot, gather + rank placement, class-grouped pair-collect
// NMS (R14 form), PARALLEL stable partition, fused gather. Resets state.
// ---------------------------------------------------------------------------
__global__ __launch_bounds__(1024) void k_select(const float* __restrict__ raw,
                                                 const float* __restrict__ vid,
                                                 const float* __restrict__ reg,
                                                 float* __restrict__ out) {
    const int b = blockIdx.x;
    const int tid = threadIdx.x;
    const int T = 1024;

    __shared__ unsigned long long keys[1024];
    __shared__ unsigned cnts[NBIN];
    __shared__ unsigned prefs[NBIN];
    __shared__ float bx1[PRE], by1[PRE], bx2[PRE], by2[PRE], barea[PRE];
    __shared__ int bcls[PRE];
    __shared__ int keep[PRE];
    __shared__ unsigned pairs[1024];
    __shared__ int members[PRE];
    __shared__ int ccnt[NCn], cstart[NCn], coff[NCn];
    __shared__ int sh_final[POST];
    __shared__ unsigned hist[256];
    __shared__ unsigned wsum[32];
    __shared__ unsigned long long sh_prefix;
    __shared__ unsigned sh_k;
    __shared__ int sh_pos, sh_maxbits, sh_np, sh_fallback;
    __shared__ int sh_p, sh_total, sh_over;

    const float* ms = g_maxs + (size_t)b * An;
    const int* cl = g_cls + (size_t)b * An;
    unsigned* BC = g_bcnt + (size_t)b * NBIN;

    int counted = g_cnt[b];

    // ---- load counts (2 bins/thread), block scan, pivot bin ----
    uint2 c2 = ((const uint2*)BC)[tid];
    cnts[2 * tid] = c2.x;
    cnts[2 * tid + 1] = c2.y;
    unsigned s = c2.x + c2.y;

    unsigned lane = tid & 31, wid = tid >> 5;
    unsigned v = s;
#pragma unroll
    for (int o = 1; o < 32; o <<= 1) {
        unsigned n = __shfl_up_sync(0xFFFFFFFFu, v, o);
        if (lane >= o) v += n;
    }
    if (lane == 31) wsum[wid] = v;
    if (tid == 0) { sh_over = 0; sh_p = -1; sh_total = 0; }
    __syncthreads();
    if (wid == 0) {
        unsigned w = wsum[lane];
#pragma unroll
        for (int o = 1; o < 32; o <<= 1) {
            unsigned n = __shfl_up_sync(0xFFFFFFFFu, w, o);
            if (lane >= o) w += n;
        }
        wsum[lane] = w;
    }
    __syncthreads();
    unsigned incl = v + (wid ? wsum[wid - 1] : 0u);
    unsigned excl = incl - s;
    prefs[2 * tid] = excl;
    prefs[2 * tid + 1] = excl + c2.x;

    if (excl < PRE && incl >= PRE) {
        int p = (excl + c2.x >= PRE) ? (2 * tid) : (2 * tid + 1);
        sh_p = p;
        sh_total = (int)(prefs[p] + cnts[p]);
    }
    __syncthreads();
    int p = sh_p;
    int total = sh_total;
    if ((int)(2 * tid) <= p && c2.x > BCAP) sh_over = 1;
    if ((int)(2 * tid + 1) <= p && c2.y > BCAP) sh_over = 1;
    __syncthreads();

    bool fastpath = (counted >= PRE) && (p >= 0) && (total <= 1024) && !sh_over;

    if (fastpath) {
        // ---- gather + rank placement (bins strictly score-separated) ----
        if (tid < total) {
            int lo = 0, hi = p;
            while (lo < hi) {
                int mid = (lo + hi + 1) >> 1;
                if (prefs[mid] <= (unsigned)tid) lo = mid; else hi = mid - 1;
            }
            unsigned k = (unsigned)tid - prefs[lo];
            const unsigned long long* src = g_bucket + ((size_t)b * NBIN + lo) * BCAP;
            unsigned long long key = src[k];
            unsigned cnt = cnts[lo];
            int rank = 0;
            for (unsigned m = 0; m < cnt; ++m)
                rank += (src[m] > key);
            keys[prefs[lo] + rank] = key;
        } else {
            keys[tid] = 0ULL;
        }
        __syncthreads();
    } else {
        // ---- exact fallback: 8-pass 64-bit radix select + block bitonic ----
        unsigned long long prefix = 0ULL;
        unsigned kk = PRE;
        const int ITER = (An + T - 1) / T;
        for (int pass = 0; pass < 8; ++pass) {
            int shift = 56 - pass * 8;
            unsigned long long hi_mask = (pass == 0) ? 0ULL : (~0ULL << (unsigned)(shift + 8));
            for (int i = tid; i < 256; i += T) hist[i] = 0;
            __syncthreads();
            for (int it = 0; it < ITER; ++it) {
                int a = it * T + tid;
                if (a < An) {
                    unsigned long long key =
                        ((unsigned long long)__float_as_uint(ms[a]) << 32) | (unsigned)(~a);
                    if ((key & hi_mask) == prefix)
                        atomicAdd(&hist[(unsigned)(key >> shift) & 255u], 1u);
                }
            }
            __syncthreads();
            if (tid == 0) {
                unsigned cum = 0; int d = 255;
                for (; d >= 0; --d) {
                    unsigned c = hist[d];
                    if (cum + c >= kk) break;
                    cum += c;
                }
                if (d < 0) d = 0;
                prefix |= ((unsigned long long)d) << shift;
                kk -= cum;
                sh_prefix = prefix; sh_k = kk;
            }
            __syncthreads();
            prefix = sh_prefix; kk = sh_k;
            __syncthreads();
        }
        if (tid == 0) sh_pos = 0;
        __syncthreads();
        for (int a = tid; a < An; a += T) {
            unsigned long long key =
                ((unsigned long long)__float_as_uint(ms[a]) << 32) | (unsigned)(~a);
            if (key >= prefix) {
                int pos = atomicAdd(&sh_pos, 1);
                if (pos < 1024) keys[pos] = key;
            }
        }
        __syncthreads();
        int cpos = sh_pos; if (cpos > 1024) cpos = 1024;
        for (int i = cpos + tid; i < 1024; i += T) keys[i] = 0ULL;
        __syncthreads();
        unsigned long long vv = keys[tid];
        for (int k2 = 2; k2 <= 1024; k2 <<= 1) {
            bool dirmax = ((tid & k2) == 0);
            for (int j = k2 >> 1; j >= 1; j >>= 1) {
                unsigned long long o;
                if (j >= 32) {
                    keys[tid] = vv;
                    __syncthreads();
                    o = keys[tid ^ j];
                    __syncthreads();
                } else {
                    o = __shfl_xor_sync(0xFFFFFFFFu, vv, j);
                }
                bool lower = ((tid & j) == 0);
                bool takeMax = (lower == dirmax);
                bool gt = (vv > o);
                vv = (takeMax == gt) ? vv : o;
            }
        }
        keys[tid] = vv;
        __syncthreads();
    }

    // reset global state for graph replay (after all reads of BC)
    ((uint2*)BC)[tid] = make_uint2(0, 0);
    if (tid == 0) g_cnt[b] = 0;

    // ---- boxes/classes for sorted top-750; max coordinate ----
    if (tid == 0) { sh_maxbits = 0; sh_fallback = 0; sh_np = 0; }
    if (tid < NCn) ccnt[tid] = 0;
    __syncthreads();
    if (tid < PRE) {
        int i = tid;
        int a = (int)(~(unsigned)(keys[i] & 0xFFFFFFFFULL));
        const float* rb = raw + (size_t)b * 84 * An;
        float x1 = rb[0 * (size_t)An + a];
        float y1 = rb[1 * (size_t)An + a];
        float x2 = rb[2 * (size_t)An + a];
        float y2 = rb[3 * (size_t)An + a];
        bx1[i] = x1; by1[i] = y1; bx2[i] = x2; by2[i] = y2;
        bcls[i] = cl[a];
        float m = fmaxf(fmaxf(x1, y1), fmaxf(x2, y2));
        atomicMax(&sh_maxbits, __float_as_int(m));
        keep[i] = 1;
        atomicAdd(&ccnt[cl[a]], 1);
    }
    __syncthreads();

    float off_scale = __int_as_float(sh_maxbits) + 1.0f;
    if (tid < PRE) {
        int i = tid;
        float off = (float)bcls[i] * off_scale;
        float x1 = bx1[i] + off, y1 = by1[i] + off;
        float x2 = bx2[i] + off, y2 = by2[i] + off;
        bx1[i] = x1; by1[i] = y1; bx2[i] = x2; by2[i] = y2;
        barea[i] = (x2 - x1) * (y2 - y1);
    }
    // warp-parallel class prefix (warp 0, 3 bins/lane: 32*3 >= 80)
    if (tid < 32) {
        int l0 = tid * 3;
        int v0 = (l0 + 0 < NCn) ? ccnt[l0 + 0] : 0;
        int v1 = (l0 + 1 < NCn) ? ccnt[l0 + 1] : 0;
        int v2 = (l0 + 2 < NCn) ? ccnt[l0 + 2] : 0;
        int lsum = v0 + v1 + v2;
        int sc = lsum;
#pragma unroll
        for (int o = 1; o < 32; o <<= 1) {
            int n = __shfl_up_sync(0xFFFFFFFFu, sc, o);
            if ((int)tid >= o) sc += n;
        }
        int ex = sc - lsum;
        if (l0 + 0 < NCn) { cstart[l0 + 0] = ex;           coff[l0 + 0] = ex; }
        if (l0 + 1 < NCn) { cstart[l0 + 1] = ex + v0;      coff[l0 + 1] = ex + v0; }
        if (l0 + 2 < NCn) { cstart[l0 + 2] = ex + v0 + v1; coff[l0 + 2] = ex + v0 + v1; }
    }
    __syncthreads();

    // ---- class-grouped pair-collect NMS (R14 measured-good form) ----
    if (tid < PRE) {
        int pos = atomicAdd(&coff[bcls[tid]], 1);
        members[pos] = tid;
    }
    __syncthreads();
    if (tid < PRE) {
        int j = tid, c = bcls[j];
        int s0 = cstart[c], e0 = s0 + ccnt[c];
        float jx1 = bx1[j], jy1 = by1[j], jx2 = bx2[j], jy2 = by2[j], ja = barea[j];
        for (int k = s0; k < e0; ++k) {
            int i = members[k];
            if (i < j) {
                float iw = fmaxf(fminf(bx2[i], jx2) - fmaxf(bx1[i], jx1), 0.0f);
                float ih = fmaxf(fminf(by2[i], jy2) - fmaxf(by1[i], jy1), 0.0f);
                float inter = iw * ih;
                float iou = __fdiv_rn(inter, barea[i] + ja - inter);
                if (iou > 0.4f) {
                    int kk = atomicAdd(&sh_np, 1);
                    if (kk < 1024) pairs[kk] = ((unsigned)i << 10) | (unsigned)j;
                }
            }
        }
    }
    __syncthreads();
    {
        int np = sh_np;
        if (np <= 1024) {
            if (tid == 0) {
                for (int a2 = 1; a2 < np; ++a2) {
                    unsigned pv = pairs[a2];
                    int b2 = a2 - 1;
                    while (b2 >= 0 && pairs[b2] > pv) { pairs[b2 + 1] = pairs[b2]; --b2; }
                    pairs[b2 + 1] = pv;
                }
                for (int p2 = 0; p2 < np; ++p2) {
                    unsigned pv = pairs[p2];
                    int i = (int)(pv >> 10), j = (int)(pv & 1023u);
                    if (keep[i]) keep[j] = 0;
                }
            }
        } else {
            if (tid == 0) sh_fallback = 1;
        }
        __syncthreads();
    }

    if (sh_fallback) {  // pathological conflict counts only: barrier-iterative
        if (tid < PRE) keep[tid] = 1;
        __syncthreads();
        int i = 0, kept = 0;
        while (i < PRE && kept < POST) {
            while (i < PRE && !keep[i]) ++i;
            if (i >= PRE) break;
            float X1 = bx1[i], Y1 = by1[i], X2 = bx2[i], Y2 = by2[i], AR = barea[i];
            int CI = bcls[i];
            for (int j = i + 1 + tid; j < PRE; j += T) {
                if (keep[j] && bcls[j] == CI) {
                    float iw = fmaxf(fminf(X2, bx2[j]) - fmaxf(X1, bx1[j]), 0.0f);
                    float ih = fmaxf(fminf(Y2, by2[j]) - fmaxf(Y1, by1[j]), 0.0f);
                    float inter = iw * ih;
                    float iou = __fdiv_rn(inter, AR + barea[j] - inter);
                    if (iou > 0.4f) keep[j] = 0;
                }
            }
            ++kept; ++i;
            __syncthreads();
        }
    }

    // ---- parallel stable partition via block scan over keep[] ----
    {
        int kv = (tid < PRE) ? keep[tid] : 0;
        int sc = kv;
#pragma unroll
        for (int o = 1; o < 32; o <<= 1) {
            int n = __shfl_up_sync(0xFFFFFFFFu, sc, o);
            if ((int)lane >= o) sc += n;
        }
        if (lane == 31) wsum[wid] = (unsigned)sc;
        __syncthreads();
        if (wid == 0) {
            int w = (int)wsum[lane];
#pragma unroll
            for (int o = 1; o < 32; o <<= 1) {
                int n = __shfl_up_sync(0xFFFFFFFFu, w, o);
                if ((int)lane >= o) w += n;
            }
            wsum[lane] = (unsigned)w;
        }
        __syncthreads();
        int kincl = sc + (wid ? (int)wsum[wid - 1] : 0);
        int kexcl = kincl - kv;
        int keptTotal = (int)wsum[31];
        if (tid < PRE) {
            int r = kv ? kexcl : (keptTotal + ((int)tid - kexcl));
            if (r < POST) sh_final[r] = tid;
        }
    }
    __syncthreads();

    // ---- fused gather ----
    for (int w2 = tid; w2 < POST * 128; w2 += T) {
        int c = w2 >> 7;
        int f = w2 & 127;
        int i = sh_final[c];
        int a = (int)(~(unsigned)(keys[i] & 0xFFFFFFFFULL));
        size_t r = (size_t)b * POST + c;
        size_t row = ((size_t)b * An + a) * CH;
        if (f < 64)
            ((float4*)(out + OUT_CLS_OFF))[r * 64 + f] = __ldg((const float4*)(vid + row) + f);
        else
            ((float4*)(out + OUT_REG_OFF))[r * 64 + (f - 64)] = __ldg((const float4*)(reg + row) + (f - 64));
    }
    if (tid < POST * 4) {
        int c = tid >> 2, d = tid & 3;
        int i = sh_final[c];
        int a = (int)(~(unsigned)(keys[i] & 0xFFFFFFFFULL));
        out[OUT_BOX_OFF + (b * POST + c) * 4 + d] = raw[(size_t)b * 84 * An + (size_t)d * An + a];
    }
    if (tid >= 128 && tid < 128 + POST) {
        int c = tid - 128;
        int i = sh_final[c];
        out[OUT_SC_OFF + b * POST + c] = __uint_as_float((unsigned)(keys[i] >> 32));
    }
}

// ---------------------------------------------------------------------------
extern "C" void kernel_launch(void* const* d_in, const int* in_sizes, int n_in,
                              void* d_out, int out_size) {
    const float* raw = (const float*)d_in[0];
    const float* vid = (const float*)d_in[1];
    const float* reg = (const float*)d_in[2];
    float* out = (float*)d_out;

    dim3 g1(FBLK, Bn);
    k_max_scatter<<<g1, 256>>>(raw);
    k_select<<<Bn, 1024>>>(raw, vid, reg, out);
}